// round 13
// baseline (speedup 1.0000x reference)
#include <cuda_runtime.h>
#include <cuda_bf16.h>

// EEBasis: out[n, 0, s] = exp(-|zeta[s]| * sqrt(diffs[n, center_idxs[s], 3]))
// N = 262144 rows, 64 centers (float4: dx,dy,dz,r2), 256 shells (4/center).
//
// R2 structure (fastest across R1-R12 sweep: split-half MLP2, unit-stride
// streams, __ldcs loads, 256-thread flat grid) with ONE change:
// stores use st.global.wt (__stwt, write-through) instead of __stcs.
// Mechanism: __stcs still allocates dirty L2 lines whose deferred
// writebacks collide with demand reads at the LTS<->DRAM interface;
// write-through drains the (fully-coalesced, full-line) write stream
// immediately and smoothly, targeting the read/write turnaround residual
// that holds this kernel at ~80% of spec HBM.
//
// Sweep evidence: MLP=4 overflows the L1tex queue (R3); persistent loops
// serialize the stream (R4); intra-thread-adjacent pairs double L1
// wavefronts (R5); block-local / 512-thr / scalar-.w / L2::256B all
// neutral (R6, R7, R10, R11).

__global__ void __launch_bounds__(256) eebasis_kernel(
    const float4* __restrict__ diffs,       // [N*64] float4
    const float4* __restrict__ zetas4,      // [64] float4 (256 zetas)
    const int*    __restrict__ center_idxs, // [256]
    float4*       __restrict__ out,         // [N*64] float4
    int half)                                // total/2
{
    int i0 = blockIdx.x * blockDim.x + threadIdx.x;
    if (i0 >= half) return;
    int i1 = i0 + half;

    int g0 = i0 & 63, n0 = i0 >> 6;
    int g1 = i1 & 63, n1 = i1 >> 6;

    // gather table (1KB, L1-resident)
    int c0 = __ldg(&center_idxs[4 * g0]);
    int c1 = __ldg(&center_idxs[4 * g1]);

    // front-batched streaming loads (MLP = 2), each unit-stride across warp
    float4 d0 = __ldcs(&diffs[n0 * 64 + c0]);
    float4 d1 = __ldcs(&diffs[n1 * 64 + c1]);

    float4 z0 = __ldg(&zetas4[g0]);   // 1KB table, L1-resident
    float4 z1 = __ldg(&zetas4[g1]);

    float r0 = sqrtf(d0.w);
    float r1 = sqrtf(d1.w);

    float4 o0, o1;
    o0.x = __expf(-fabsf(z0.x) * r0);
    o0.y = __expf(-fabsf(z0.y) * r0);
    o0.z = __expf(-fabsf(z0.z) * r0);
    o0.w = __expf(-fabsf(z0.w) * r0);

    o1.x = __expf(-fabsf(z1.x) * r1);
    o1.y = __expf(-fabsf(z1.y) * r1);
    o1.z = __expf(-fabsf(z1.z) * r1);
    o1.w = __expf(-fabsf(z1.w) * r1);

    // write-through streaming stores (full-line coalesced per warp)
    __stwt(&out[i0], o0);
    __stwt(&out[i1], o1);
}

extern "C" void kernel_launch(void* const* d_in, const int* in_sizes, int n_in,
                              void* d_out, int out_size)
{
    const float* diffs       = (const float*)d_in[0];  // [N, 64, 4] f32
    const float* zetas       = (const float*)d_in[1];  // [256] f32
    const int*   center_idxs = (const int*)  d_in[2];  // [256] i32

    int n_rows = in_sizes[0] / (64 * 4);
    int total  = n_rows * 64;
    int half   = total / 2;   // N is a power of two; total even

    int threads = 256;
    int blocks  = (half + threads - 1) / threads;

    eebasis_kernel<<<blocks, threads>>>(
        (const float4*)diffs,
        (const float4*)zetas,
        center_idxs,
        (float4*)d_out,
        half);
}

// round 14
// speedup vs baseline: 1.0051x; 1.0051x over previous
#include <cuda_runtime.h>
#include <cuda_bf16.h>

// EEBasis: out[n, 0, s] = exp(-|zeta[s]| * sqrt(diffs[n, center_idxs[s], 3]))
// N = 262144 rows, 64 centers (float4: dx,dy,dz,r2), 256 shells (4/center).
//
// FINAL — R2 configuration, fastest across the complete R1-R13 sweep.
// Float4-linear input index == float4-linear output index (shells are
// center-grouped). Both 256 MiB streams are single-touch:
//  - __ldcs loads (evict-first: no L2 pollution)
//  - __stcs stores (streaming; beats both default and write-through __stwt
//    — L2's write-coalescing buffer smooths the DRAM write schedule, R13)
//  - 2 items per thread, split total/2 apart: both streams unit-stride
//    across the warp (4 lines per LDG.128), loads front-batched (MLP=2)
//  - 256-thread flat grid (32768 CTAs)
//
// Sweep evidence (kernel-time / DRAM%):
//   MLP1 84.3/73.5 | MLP2 split-half 75.3-75.8/80-81 (THIS) | MLP4 76.6/80.0
//   persistent loop 81.1/75.6 (loop-carry serializes the request stream)
//   intra-thread-adjacent 83.0/73.5 (doubles L1 wavefronts per load)
//   block-local 76.4 | 512-thr 76.7 | scalar-.w 76.1 | L2::256B 76.0
//   __stwt stores 76.8/78.9
// 6.38 TB/s achieved = ~93% of the LTS chip cap on a 1:1 R:W mixed stream;
// the 512 MiB traffic floor is fixed by 32B-sector granularity. The
// residual vs spec is DRAM bus turnaround, unreachable from the SM side.

__global__ void __launch_bounds__(256) eebasis_kernel(
    const float4* __restrict__ diffs,       // [N*64] float4
    const float4* __restrict__ zetas4,      // [64] float4 (256 zetas)
    const int*    __restrict__ center_idxs, // [256]
    float4*       __restrict__ out,         // [N*64] float4
    int half)                                // total/2
{
    int i0 = blockIdx.x * blockDim.x + threadIdx.x;
    if (i0 >= half) return;
    int i1 = i0 + half;

    int g0 = i0 & 63, n0 = i0 >> 6;
    int g1 = i1 & 63, n1 = i1 >> 6;

    // gather table (1KB, L1-resident)
    int c0 = __ldg(&center_idxs[4 * g0]);
    int c1 = __ldg(&center_idxs[4 * g1]);

    // front-batched streaming loads (MLP = 2), each unit-stride across warp
    float4 d0 = __ldcs(&diffs[n0 * 64 + c0]);
    float4 d1 = __ldcs(&diffs[n1 * 64 + c1]);

    float4 z0 = __ldg(&zetas4[g0]);   // 1KB table, L1-resident
    float4 z1 = __ldg(&zetas4[g1]);

    float r0 = sqrtf(d0.w);
    float r1 = sqrtf(d1.w);

    float4 o0, o1;
    o0.x = __expf(-fabsf(z0.x) * r0);
    o0.y = __expf(-fabsf(z0.y) * r0);
    o0.z = __expf(-fabsf(z0.z) * r0);
    o0.w = __expf(-fabsf(z0.w) * r0);

    o1.x = __expf(-fabsf(z1.x) * r1);
    o1.y = __expf(-fabsf(z1.y) * r1);
    o1.z = __expf(-fabsf(z1.z) * r1);
    o1.w = __expf(-fabsf(z1.w) * r1);

    __stcs(&out[i0], o0);
    __stcs(&out[i1], o1);
}

extern "C" void kernel_launch(void* const* d_in, const int* in_sizes, int n_in,
                              void* d_out, int out_size)
{
    const float* diffs       = (const float*)d_in[0];  // [N, 64, 4] f32
    const float* zetas       = (const float*)d_in[1];  // [256] f32
    const int*   center_idxs = (const int*)  d_in[2];  // [256] i32

    int n_rows = in_sizes[0] / (64 * 4);
    int total  = n_rows * 64;
    int half   = total / 2;   // N is a power of two; total even

    int threads = 256;
    int blocks  = (half + threads - 1) / threads;

    eebasis_kernel<<<blocks, threads>>>(
        (const float4*)diffs,
        (const float4*)zetas,
        center_idxs,
        (float4*)d_out,
        half);
}

// round 15
// speedup vs baseline: 1.0078x; 1.0027x over previous
#include <cuda_runtime.h>
#include <cuda_bf16.h>

// EEBasis: out[n, 0, s] = exp(-|zeta[s]| * sqrt(diffs[n, center_idxs[s], 3]))
// N = 262144 rows, 64 centers (float4: dx,dy,dz,r2), 256 shells (4/center).
//
// FINAL — R2 configuration, fastest across the complete R1-R14 sweep.
// Float4-linear input index == float4-linear output index (shells are
// center-grouped). Both 256 MiB streams are single-touch:
//  - __ldcs loads (evict-first: no L2 pollution)
//  - __stcs stores (streaming; beats default AND write-through __stwt —
//    L2's write-coalescing buffer smooths the DRAM write schedule, R13)
//  - 2 items per thread, split total/2 apart: both streams unit-stride
//    across the warp (4 lines per LDG.128), loads front-batched (MLP=2)
//  - 256-thread flat grid (32768 CTAs)
//
// Sweep evidence (kernel-time / DRAM%):
//   MLP1 84.3/73.5 | MLP2 split-half 75.3-77.1/79-81 (THIS) | MLP4 76.6/80.0
//   persistent loop 81.1/75.6 (loop-carry serializes the request stream)
//   intra-thread-adjacent 83.0/73.5 (doubles L1 wavefronts per load)
//   block-local 76.4 | 512-thr 76.7 | scalar-.w 76.1 | L2::256B 76.0
//   __stwt stores 76.8/78.9
// 6.3-6.4 TB/s = ~93% of the LTS chip cap on a 1:1 R:W mixed stream; the
// 512 MiB traffic floor is fixed by 32B-sector granularity (r2 values sit
// at +12/+28 in every 32B sector — no read savings possible). Residual vs
// spec is DRAM bus turnaround, unreachable from the SM side (falsified:
// MLP depth, promotion hints, write-through, scheduling, locality).
// Session-level dur drift (80.35 -> 82.0 us on identical binaries) is
// container clock state, not kernel.

__global__ void __launch_bounds__(256) eebasis_kernel(
    const float4* __restrict__ diffs,       // [N*64] float4
    const float4* __restrict__ zetas4,      // [64] float4 (256 zetas)
    const int*    __restrict__ center_idxs, // [256]
    float4*       __restrict__ out,         // [N*64] float4
    int half)                                // total/2
{
    int i0 = blockIdx.x * blockDim.x + threadIdx.x;
    if (i0 >= half) return;
    int i1 = i0 + half;

    int g0 = i0 & 63, n0 = i0 >> 6;
    int g1 = i1 & 63, n1 = i1 >> 6;

    // gather table (1KB, L1-resident)
    int c0 = __ldg(&center_idxs[4 * g0]);
    int c1 = __ldg(&center_idxs[4 * g1]);

    // front-batched streaming loads (MLP = 2), each unit-stride across warp
    float4 d0 = __ldcs(&diffs[n0 * 64 + c0]);
    float4 d1 = __ldcs(&diffs[n1 * 64 + c1]);

    float4 z0 = __ldg(&zetas4[g0]);   // 1KB table, L1-resident
    float4 z1 = __ldg(&zetas4[g1]);

    float r0 = sqrtf(d0.w);
    float r1 = sqrtf(d1.w);

    float4 o0, o1;
    o0.x = __expf(-fabsf(z0.x) * r0);
    o0.y = __expf(-fabsf(z0.y) * r0);
    o0.z = __expf(-fabsf(z0.z) * r0);
    o0.w = __expf(-fabsf(z0.w) * r0);

    o1.x = __expf(-fabsf(z1.x) * r1);
    o1.y = __expf(-fabsf(z1.y) * r1);
    o1.z = __expf(-fabsf(z1.z) * r1);
    o1.w = __expf(-fabsf(z1.w) * r1);

    __stcs(&out[i0], o0);
    __stcs(&out[i1], o1);
}

extern "C" void kernel_launch(void* const* d_in, const int* in_sizes, int n_in,
                              void* d_out, int out_size)
{
    const float* diffs       = (const float*)d_in[0];  // [N, 64, 4] f32
    const float* zetas       = (const float*)d_in[1];  // [256] f32
    const int*   center_idxs = (const int*)  d_in[2];  // [256] i32

    int n_rows = in_sizes[0] / (64 * 4);
    int total  = n_rows * 64;
    int half   = total / 2;   // N is a power of two; total even

    int threads = 256;
    int blocks  = (half + threads - 1) / threads;

    eebasis_kernel<<<blocks, threads>>>(
        (const float4*)diffs,
        (const float4*)zetas,
        center_idxs,
        (float4*)d_out,
        half);
}